// round 11
// baseline (speedup 1.0000x reference)
#include <cuda_runtime.h>
#include <math.h>

// ---------------------------------------------------------------------------
// Problem constants (fixed shapes)
// ---------------------------------------------------------------------------
#define NN    4096
#define EE    131072
#define FEATD 64
#define HIDD  256
#define NHEAD 4
#define DHD   64
#define NEGV  (-1e9f)

// ---------------------------------------------------------------------------
// Device scratch (no dynamic allocation allowed)
// ---------------------------------------------------------------------------
__device__ float g_h0[NN * HIDD];
__device__ float g_x [NN * HIDD];
__device__ float g_H [NN * HIDD];
__device__ float g_cat[NN * 2 * HIDD];      // [xg | h0] concat, K=512 GEMM input
__device__ float g_C [NN * HIDD];
__device__ float g_q [NN * HIDD];
__device__ float g_k [NN * HIDD];
__device__ float g_v [NN * HIDD];
__device__ float g_hv[NN * HIDD];
__device__ float g_el[NN * NHEAD];
__device__ float g_er[NN * NHEAD];
__device__ float g_m [NN * NHEAD];
__device__ float g_we[EE * NHEAD];          // leaky-relu edge scores (immutable)
__device__ float g_yhat[NN];
__device__ float g_xyz0[NN * 3];
__device__ float g_xyz1[NN * 3];
__device__ unsigned char g_mask[(size_t)NN * NN];
__device__ float g_S[(size_t)NN * NN];
__device__ int   g_mask_type;   // 0 = uint8, 1 = int32, 2 = float32
// CSR-by-dst (built once per launch; dst is layer-invariant)
__device__ int g_deg[NN];
__device__ int g_cnt[NN];
__device__ int g_off[NN + 1];
__device__ int g_eid[EE];

// ---------------------------------------------------------------------------
// Packed f32x2 helpers (Blackwell FFMA2 — only reachable via PTX)
// ---------------------------------------------------------------------------
__device__ __forceinline__ unsigned long long packf2(float x, float y) {
    unsigned long long r;
    asm("mov.b64 %0, {%1, %2};" : "=l"(r) : "f"(x), "f"(y));
    return r;
}
__device__ __forceinline__ void unpackf2(unsigned long long v, float& x, float& y) {
    asm("mov.b64 {%0, %1}, %2;" : "=f"(x), "=f"(y) : "l"(v));
}
__device__ __forceinline__ void ffma2(unsigned long long& d,
                                      unsigned long long a,
                                      unsigned long long b) {
    asm("fma.rn.f32x2 %0, %1, %2, %0;" : "+l"(d) : "l"(a), "l"(b));
}

__device__ __forceinline__ void atomicMaxFloat(float* addr, float val) {
    int* ia = (int*)addr;
    int old = *ia;
    while (__int_as_float(old) < val) {
        int assumed = old;
        old = atomicCAS(ia, assumed, __float_as_int(val));
        if (old == assumed) break;
    }
}

// ---------------------------------------------------------------------------
// Software-pipelined, double-buffered SGEMM with packed f32x2 FMA.
// A tiles live in SMEM pre-duplicated as u64 [a|a]. Ping-pong buffers give
// ONE __syncthreads per k-iteration.
//   C[M,Nc](ldc=Nc) = alpha * A[M,K] * op(B) (+bias) (+C) (relu)
//   op(B) = B[K,Nc] (TRANSB=0) or B[Nc,K]^T (TRANSB=1)
// MASKED=1 (score mode): out = mask && sqi+sqj-2dot<=100
//                              ? acc*alpha - |yhat_r-yhat_c| : NEGV
//   (d2 uses the reference's sq[i]+sq[j]-2*dot formula)
// Tiles: BM=128 x BN(64|128) x BK=16, 256 threads.
// REQUIRES: M%128==0, Nc%BN==0, K%16==0.
// ---------------------------------------------------------------------------
template<int BN, int TRANSB, int ACC, int RELU, int MASKED = 0>
__device__ __forceinline__ void gemm128_body(const float* __restrict__ A,
                                             const float* __restrict__ B,
                                             const float* __restrict__ bias,
                                             float* __restrict__ C,
                                             int M, int Nc, int K, float alpha,
                                             const float* __restrict__ mxyz = nullptr,
                                             const float* __restrict__ myhat = nullptr)
{
    const int BM = 128, BK = 16;
    const int TN = BN / 16;
    const int J2 = BN / 32;
    const int NB = BN / 64;     // B float4 loads per thread (1 or 2)

    __shared__ unsigned long long As[2][BK][BM];   // duplicated-lane A
    __shared__ float Bs[2][BK][BN];

    int tid = threadIdx.x;
    int tx = tid & 15, ty = tid >> 4;
    int row0 = blockIdx.y * BM;
    int col0 = blockIdx.x * BN;

    const int ar0 = (tid + 0)   >> 2, ac0 = ((tid + 0)   & 3) * 4;
    const int ar1 = (tid + 256) >> 2, ac1 = ((tid + 256) & 3) * 4;

    unsigned long long acc[8][J2];
#pragma unroll
    for (int i = 0; i < 8; i++)
#pragma unroll
        for (int j = 0; j < J2; j++) acc[i][j] = 0ull;

    float4 aReg[2];
    float4 bReg[NB];

    // ---- prologue: load tile 0 into registers, stage into buffer 0 ----
    aReg[0] = *reinterpret_cast<const float4*>(A + (size_t)(row0 + ar0) * K + ac0);
    aReg[1] = *reinterpret_cast<const float4*>(A + (size_t)(row0 + ar1) * K + ac1);
#pragma unroll
    for (int t = 0; t < NB; t++) {
        int idx = tid + t * 256;
        if (TRANSB) {
            int r = idx >> 2, c4 = (idx & 3) * 4;
            bReg[t] = *reinterpret_cast<const float4*>(B + (size_t)(col0 + r) * K + c4);
        } else {
            int kk = idx / (BN / 4), c4 = (idx % (BN / 4)) * 4;
            bReg[t] = *reinterpret_cast<const float4*>(B + (size_t)kk * Nc + col0 + c4);
        }
    }
    As[0][ac0 + 0][ar0] = packf2(aReg[0].x, aReg[0].x);
    As[0][ac0 + 1][ar0] = packf2(aReg[0].y, aReg[0].y);
    As[0][ac0 + 2][ar0] = packf2(aReg[0].z, aReg[0].z);
    As[0][ac0 + 3][ar0] = packf2(aReg[0].w, aReg[0].w);
    As[0][ac1 + 0][ar1] = packf2(aReg[1].x, aReg[1].x);
    As[0][ac1 + 1][ar1] = packf2(aReg[1].y, aReg[1].y);
    As[0][ac1 + 2][ar1] = packf2(aReg[1].z, aReg[1].z);
    As[0][ac1 + 3][ar1] = packf2(aReg[1].w, aReg[1].w);
#pragma unroll
    for (int t = 0; t < NB; t++) {
        int idx = tid + t * 256;
        if (TRANSB) {
            int r = idx >> 2, c4 = (idx & 3) * 4;
            Bs[0][c4 + 0][r] = bReg[t].x; Bs[0][c4 + 1][r] = bReg[t].y;
            Bs[0][c4 + 2][r] = bReg[t].z; Bs[0][c4 + 3][r] = bReg[t].w;
        } else {
            int kk = idx / (BN / 4), c4 = (idx % (BN / 4)) * 4;
            *reinterpret_cast<float4*>(&Bs[0][kk][c4]) = bReg[t];
        }
    }
    __syncthreads();

    int cur = 0;
    for (int k0 = 0; k0 < K; k0 += BK) {
        int kn = k0 + BK;
        // ---- issue prefetch LDGs for next tile ----
        if (kn < K) {
            aReg[0] = *reinterpret_cast<const float4*>(A + (size_t)(row0 + ar0) * K + kn + ac0);
            aReg[1] = *reinterpret_cast<const float4*>(A + (size_t)(row0 + ar1) * K + kn + ac1);
#pragma unroll
            for (int t = 0; t < NB; t++) {
                int idx = tid + t * 256;
                if (TRANSB) {
                    int r = idx >> 2, c4 = (idx & 3) * 4;
                    bReg[t] = *reinterpret_cast<const float4*>(
                        B + (size_t)(col0 + r) * K + kn + c4);
                } else {
                    int kk = idx / (BN / 4), c4 = (idx % (BN / 4)) * 4;
                    bReg[t] = *reinterpret_cast<const float4*>(
                        B + (size_t)(kn + kk) * Nc + col0 + c4);
                }
            }
        }

        // ---- compute from current buffer ----
#pragma unroll
        for (int kk = 0; kk < BK; kk++) {
            unsigned long long a2[8];
            const unsigned long long* arow = &As[cur][kk][ty * 8];
#pragma unroll
            for (int i = 0; i < 8; i++) a2[i] = arow[i];
            const unsigned long long* brow =
                reinterpret_cast<const unsigned long long*>(&Bs[cur][kk][tx * TN]);
            unsigned long long b2[J2];
#pragma unroll
            for (int j = 0; j < J2; j++) b2[j] = brow[j];
#pragma unroll
            for (int i = 0; i < 8; i++)
#pragma unroll
                for (int j = 0; j < J2; j++) ffma2(acc[i][j], a2[i], b2[j]);
        }

        // ---- store next tile into the other buffer, single barrier ----
        if (kn < K) {
            int nxt = cur ^ 1;
            As[nxt][ac0 + 0][ar0] = packf2(aReg[0].x, aReg[0].x);
            As[nxt][ac0 + 1][ar0] = packf2(aReg[0].y, aReg[0].y);
            As[nxt][ac0 + 2][ar0] = packf2(aReg[0].z, aReg[0].z);
            As[nxt][ac0 + 3][ar0] = packf2(aReg[0].w, aReg[0].w);
            As[nxt][ac1 + 0][ar1] = packf2(aReg[1].x, aReg[1].x);
            As[nxt][ac1 + 1][ar1] = packf2(aReg[1].y, aReg[1].y);
            As[nxt][ac1 + 2][ar1] = packf2(aReg[1].z, aReg[1].z);
            As[nxt][ac1 + 3][ar1] = packf2(aReg[1].w, aReg[1].w);
#pragma unroll
            for (int t = 0; t < NB; t++) {
                int idx = tid + t * 256;
                if (TRANSB) {
                    int r = idx >> 2, c4 = (idx & 3) * 4;
                    Bs[nxt][c4 + 0][r] = bReg[t].x; Bs[nxt][c4 + 1][r] = bReg[t].y;
                    Bs[nxt][c4 + 2][r] = bReg[t].z; Bs[nxt][c4 + 3][r] = bReg[t].w;
                } else {
                    int kk = idx / (BN / 4), c4 = (idx % (BN / 4)) * 4;
                    *reinterpret_cast<float4*>(&Bs[nxt][kk][c4]) = bReg[t];
                }
            }
            __syncthreads();
            cur = nxt;
        }
    }

    // ---- epilogue ----
    if (MASKED) {
        // hoist per-thread column data (TN = 8 cols)
        float cx0[8], cx1[8], cx2[8], cy[8], csq[8];
#pragma unroll
        for (int j = 0; j < TN; j++) {
            int c = col0 + tx * TN + j;
            cx0[j] = mxyz[c * 3];
            cx1[j] = mxyz[c * 3 + 1];
            cx2[j] = mxyz[c * 3 + 2];
            cy[j]  = myhat[c];
            csq[j] = cx0[j] * cx0[j] + cx1[j] * cx1[j] + cx2[j] * cx2[j];
        }
#pragma unroll
        for (int i = 0; i < 8; i++) {
            int r = row0 + ty * 8 + i;
            float rx0 = mxyz[r * 3], rx1 = mxyz[r * 3 + 1], rx2 = mxyz[r * 3 + 2];
            float rsq = rx0 * rx0 + rx1 * rx1 + rx2 * rx2;
            float yi = myhat[r];
            const unsigned char* mrow = &g_mask[(size_t)r * NN + col0 + tx * TN];
#pragma unroll
            for (int j = 0; j < J2; j++) {
                int c = col0 + tx * TN + j * 2;
                float x, y;
                unpackf2(acc[i][j], x, y);
                x *= alpha; y *= alpha;
                float o0 = NEGV, o1 = NEGV;
                {
                    int jj = j * 2;
                    if (mrow[jj]) {
                        float dot = rx0 * cx0[jj] + rx1 * cx1[jj] + rx2 * cx2[jj];
                        float d2 = rsq + csq[jj] - 2.f * dot;   // reference formula
                        if (d2 <= 100.0f)
                            o0 = x - fabsf(yi - cy[jj]);
                    }
                    jj = j * 2 + 1;
                    if (mrow[jj]) {
                        float dot = rx0 * cx0[jj] + rx1 * cx1[jj] + rx2 * cx2[jj];
                        float d2 = rsq + csq[jj] - 2.f * dot;
                        if (d2 <= 100.0f)
                            o1 = y - fabsf(yi - cy[jj]);
                    }
                }
                *reinterpret_cast<float2*>(C + (size_t)r * Nc + c) = make_float2(o0, o1);
            }
        }
    } else {
#pragma unroll
        for (int i = 0; i < 8; i++) {
            int r = row0 + ty * 8 + i;
#pragma unroll
            for (int j = 0; j < J2; j++) {
                int c = col0 + tx * TN + j * 2;
                float x, y;
                unpackf2(acc[i][j], x, y);
                x *= alpha; y *= alpha;
                if (bias) { x += bias[c]; y += bias[c + 1]; }
                float* cp = C + (size_t)r * Nc + c;
                if (ACC) { float2 o = *reinterpret_cast<float2*>(cp); x += o.x; y += o.y; }
                if (RELU) { x = fmaxf(x, 0.f); y = fmaxf(y, 0.f); }
                *reinterpret_cast<float2*>(cp) = make_float2(x, y);
            }
        }
    }
}

template<int BN, int TRANSB, int ACC, int RELU>
__global__ void gemm128_kernel(const float* __restrict__ A,
                               const float* __restrict__ B,
                               const float* __restrict__ bias,
                               float* __restrict__ C,
                               int M, int Nc, int K, float alpha)
{
    gemm128_body<BN, TRANSB, ACC, RELU>(A, B, bias, C, M, Nc, K, alpha);
}

// Masked score GEMM: S = mask&band ? (q@k^T)/16 - |dy| : NEG
__global__ void gemm128_score_kernel(const float* __restrict__ Q,
                                     const float* __restrict__ Km,
                                     float* __restrict__ S,
                                     const float* __restrict__ xyz,
                                     const float* __restrict__ yhat)
{
    gemm128_body<128, 1, 0, 0, 1>(Q, Km, nullptr, S, NN, NN, HIDD, 1.f / 16.f,
                                  xyz, yhat);
}

// Batched QKV projection: blockIdx.z selects {q,k,v}.
struct QKVArgs {
    const float* W[3];
    const float* b[3];
    float*       O[3];
};
__global__ void gemm128_qkv_kernel(const float* __restrict__ A, QKVArgs args,
                                   int M, int Nc, int K)
{
    int z = blockIdx.z;
    gemm128_body<64, 0, 0, 0>(A, args.W[z], args.b[z], args.O[z], M, Nc, K, 1.f);
}

// ---------------------------------------------------------------------------
// Small utility kernels (float4-vectorized where traffic matters)
// ---------------------------------------------------------------------------
__global__ void gat_init_kernel() {
    int i = blockIdx.x * blockDim.x + threadIdx.x;
    if (i < NN * NHEAD) g_m[i] = -3.0e38f;
}
__global__ void fill_int_kernel(int* p, int v, int n) {
    int i = blockIdx.x * blockDim.x + threadIdx.x;
    if (i < n) p[i] = v;
}
__global__ void copy_kernel(const float* __restrict__ a, float* __restrict__ b, int n) {
    int i = blockIdx.x * blockDim.x + threadIdx.x;
    if (i < n) b[i] = a[i];
}
// copy4: n must be a multiple of 4
__global__ void copy4_kernel(const float* __restrict__ a, float* __restrict__ b, int n4) {
    int i = blockIdx.x * blockDim.x + threadIdx.x;
    if (i < n4)
        reinterpret_cast<float4*>(b)[i] = reinterpret_cast<const float4*>(a)[i];
}
// copy h0 into right half of g_cat (float4: 64 vec4 per row)
__global__ void cat_init_kernel() {
    int idx = blockIdx.x * blockDim.x + threadIdx.x;   // NN*64 vec4s
    if (idx >= NN * 64) return;
    int r = idx >> 6, c4 = idx & 63;
    reinterpret_cast<float4*>(&g_cat[(size_t)r * 512 + 256])[c4] =
        reinterpret_cast<const float4*>(&g_h0[(size_t)r * 256])[c4];
}

// Bool-mask dtype sniffer: scans the first 4096 32-bit words of distance_mask.
__global__ void detect_mask_kernel(const void* p) {
    const unsigned int* w = (const unsigned int*)p;
    __shared__ int notbool, notfloat;
    if (threadIdx.x == 0) { notbool = 0; notfloat = 0; }
    __syncthreads();
    for (int j = threadIdx.x; j < 4096; j += blockDim.x) {
        unsigned int v = w[j];
        if (v > 1u) notbool = 1;                       // benign race
        if (v != 0u && v != 0x3F800000u) notfloat = 1;
    }
    __syncthreads();
    if (threadIdx.x == 0) {
        if (!notbool)       g_mask_type = 1;   // int32 0/1
        else if (!notfloat) g_mask_type = 2;   // float32 0/1
        else                g_mask_type = 0;   // uint8
    }
}

__global__ void build_mask_kernel(const void* dm, const void* bm) {
    size_t idx = (size_t)blockIdx.x * blockDim.x + threadIdx.x;
    size_t total = (size_t)NN * NN;
    if (idx >= total) return;
    int t = g_mask_type;
    bool a, b;
    if (t == 0) {
        a = ((const unsigned char*)dm)[idx] != 0;
        b = ((const unsigned char*)bm)[idx] != 0;
    } else if (t == 1) {
        a = ((const int*)dm)[idx] != 0;
        b = ((const int*)bm)[idx] != 0;
    } else {
        a = ((const float*)dm)[idx] != 0.f;
        b = ((const float*)bm)[idx] != 0.f;
    }
    g_mask[idx] = (a && b) ? 1 : 0;
}

// ---------------------------------------------------------------------------
// CSR-by-dst construction (once per launch)
// ---------------------------------------------------------------------------
__global__ void deg_count_kernel(const int* __restrict__ dst) {
    int e = blockIdx.x * blockDim.x + threadIdx.x;
    if (e < EE) atomicAdd(&g_deg[dst[e]], 1);
}

// Single-block Hillis-Steele inclusive scan over NN=4096 counts -> g_off
__global__ void scan_kernel() {
    __shared__ int bufA[NN], bufB[NN];
    int tid = threadIdx.x;                 // 1024 threads
    for (int i = tid; i < NN; i += 1024) bufA[i] = g_deg[i];
    __syncthreads();
    int* in = bufA; int* out = bufB;
    for (int s = 1; s < NN; s <<= 1) {
        for (int i = tid; i < NN; i += 1024)
            out[i] = in[i] + ((i >= s) ? in[i - s] : 0);
        __syncthreads();
        int* t = in; in = out; out = t;
    }
    if (tid == 0) g_off[0] = 0;
    for (int i = tid; i < NN; i += 1024) g_off[i + 1] = in[i];
}

__global__ void scatter_eid_kernel(const int* __restrict__ dst) {
    int e = blockIdx.x * blockDim.x + threadIdx.x;
    if (e >= EE) return;
    int d = dst[e];
    int pos = g_off[d] + atomicAdd(&g_cnt[d], 1);
    g_eid[pos] = e;
}

// ---------------------------------------------------------------------------
// GAT kernels
// ---------------------------------------------------------------------------
__global__ void gat_attn_kernel(const float* __restrict__ H,
                                const float* __restrict__ al,
                                const float* __restrict__ ar) {
    int idx = blockIdx.x * blockDim.x + threadIdx.x;   // N * NHEAD
    if (idx >= NN * NHEAD) return;
    int i = idx >> 2, h = idx & 3;
    const float* hp = H + (size_t)i * HIDD + h * DHD;
    const float* alp = al + h * DHD;
    const float* arp = ar + h * DHD;
    float sl = 0.f, sr = 0.f;
#pragma unroll 8
    for (int d = 0; d < DHD; d++) {
        float hv = hp[d];
        sl += hv * alp[d];
        sr += hv * arp[d];
    }
    g_el[idx] = sl;
    g_er[idx] = sr;
}

__global__ void gat_edge1_kernel(const int* __restrict__ src,
                                 const int* __restrict__ dst) {
    int idx = blockIdx.x * blockDim.x + threadIdx.x;   // E * NHEAD
    if (idx >= EE * NHEAD) return;
    int e = idx >> 2, h = idx & 3;
    float s = g_el[src[e] * NHEAD + h] + g_er[dst[e] * NHEAD + h];
    float v = s > 0.f ? s : 0.2f * s;                  // leaky_relu 0.2
    g_we[idx] = v;
    atomicMaxFloat(&g_m[dst[e] * NHEAD + h], v);
}

// CSR gather with fused edge-softmax normalization.
// 4 dst nodes per block (256 thr = 4 x 64); each thread owns 4 channels
// (one head). Pass A: z = sum exp(we - m). Pass B: weighted accumulate.
// No atomics; writes the LEFT half of g_cat directly (row stride 512).
__global__ void gat_gather_kernel(const int* __restrict__ src) {
    int tid = threadIdx.x;
    int d  = blockIdx.x * 4 + (tid >> 6);   // dst node
    int t64 = tid & 63;                     // 0..63
    int c4 = t64 * 4;                       // channel base (0..252)
    int h = c4 >> 6;                        // head (4 channels share a head)
    float m = g_m[d * NHEAD + h];
    int p0 = g_off[d], p1 = g_off[d + 1];

    // pass A: normalization constant
    float z = 0.f;
    for (int p = p0; p < p1; p++) {
        int e = g_eid[p];
        z += __expf(g_we[e * NHEAD + h] - m);
    }
    float inv = 1.f / (z + 1e-9f);

    // pass B: weighted feature accumulation
    float4 acc = make_float4(0.f, 0.f, 0.f, 0.f);
    for (int p = p0; p < p1; p++) {
        int e = g_eid[p];
        float a = __expf(g_we[e * NHEAD + h] - m) * inv;
        float4 hv = *reinterpret_cast<const float4*>(
            &g_H[(size_t)src[e] * HIDD + c4]);
        acc.x += a * hv.x; acc.y += a * hv.y;
        acc.z += a * hv.z; acc.w += a * hv.w;
    }
    *reinterpret_cast<float4*>(&g_cat[(size_t)d * 512 + c4]) = acc;
}

// combine, float4: x = theta*C + (1-theta)*(0.9*xg + 0.1*h0) + x
__global__ void gnn_combine_kernel(float theta) {
    int idx = blockIdx.x * blockDim.x + threadIdx.x;   // NN*64 vec4s
    if (idx >= NN * 64) return;
    int r = idx >> 6, c4 = idx & 63;
    float4 xg = reinterpret_cast<const float4*>(&g_cat[(size_t)r * 512])[c4];
    float4 h0 = reinterpret_cast<const float4*>(&g_h0[(size_t)r * 256])[c4];
    float4 cc = reinterpret_cast<const float4*>(&g_C[(size_t)r * 256])[c4];
    float4 xx = reinterpret_cast<float4*>(&g_x[(size_t)r * 256])[c4];
    float om = 1.f - theta;
    xx.x = theta * cc.x + om * (0.9f * xg.x + 0.1f * h0.x) + xx.x;
    xx.y = theta * cc.y + om * (0.9f * xg.y + 0.1f * h0.y) + xx.y;
    xx.z = theta * cc.z + om * (0.9f * xg.z + 0.1f * h0.z) + xx.z;
    xx.w = theta * cc.w + om * (0.9f * xg.w + 0.1f * h0.w) + xx.w;
    reinterpret_cast<float4*>(&g_x[(size_t)r * 256])[c4] = xx;
}

// ---------------------------------------------------------------------------
// y_hat = softmax(x @ cls_gat_W + b)[:, 1]
// ---------------------------------------------------------------------------
__global__ void yhat_kernel(const float* __restrict__ W, const float* __restrict__ b) {
    int i = blockIdx.x * blockDim.x + threadIdx.x;
    if (i >= NN) return;
    float l0 = b[0], l1 = b[1];
    const float* xp = g_x + (size_t)i * HIDD;
#pragma unroll 8
    for (int kk = 0; kk < HIDD; kk++) {
        float xv = xp[kk];
        l0 += xv * W[kk * 2 + 0];
        l1 += xv * W[kk * 2 + 1];
    }
    float m = fmaxf(l0, l1);
    float e0 = __expf(l0 - m), e1 = __expf(l1 - m);
    g_yhat[i] = e1 / (e0 + e1);
}

// Final classifier: out[i,:] = x[i,:] @ clsW + clsb   (Nc = 2)
__global__ void cls_kernel(const float* __restrict__ W,
                           const float* __restrict__ b,
                           float* __restrict__ out) {
    int i = blockIdx.x * blockDim.x + threadIdx.x;
    if (i >= NN) return;
    float l0 = b[0], l1 = b[1];
    const float* xp = g_x + (size_t)i * HIDD;
#pragma unroll 8
    for (int kk = 0; kk < HIDD; kk++) {
        float xv = xp[kk];
        l0 += xv * W[kk * 2 + 0];
        l1 += xv * W[kk * 2 + 1];
    }
    out[i * 2 + 0] = l0;
    out[i * 2 + 1] = l1;
}

// ---------------------------------------------------------------------------
// Softmax over a pre-masked score row (held in SMEM) + fused attn @ xyz.
// All row passes vectorized as float4 (NN % (NT*4) == 0, rows 16B-aligned).
// ---------------------------------------------------------------------------
__global__ void ms_softmax_kernel(const float* __restrict__ xyz,
                                  float* __restrict__ xyz_out)
{
    __shared__ float sv[NN];
    __shared__ float red[512];
    const int NT = 512;
    int i = blockIdx.x, tid = threadIdx.x;
    size_t rowoff = (size_t)i * NN;

    // pass 1: load scores (float4), track max
    float lmax = -3.4e38f;
    for (int j4 = tid * 4; j4 < NN; j4 += NT * 4) {
        float4 v = *reinterpret_cast<const float4*>(&g_S[rowoff + j4]);
        *reinterpret_cast<float4*>(&sv[j4]) = v;
        lmax = fmaxf(lmax, fmaxf(fmaxf(v.x, v.y), fmaxf(v.z, v.w)));
    }
    red[tid] = lmax; __syncthreads();
    for (int s = NT / 2; s > 0; s >>= 1) {
        if (tid < s) red[tid] = fmaxf(red[tid], red[tid + s]);
        __syncthreads();
    }
    float rmax = red[0]; __syncthreads();

    // pass 2: exp + sum (float4)
    float lsum = 0.f;
    for (int j4 = tid * 4; j4 < NN; j4 += NT * 4) {
        float4 v = *reinterpret_cast<float4*>(&sv[j4]);
        v.x = __expf(v.x - rmax); v.y = __expf(v.y - rmax);
        v.z = __expf(v.z - rmax); v.w = __expf(v.w - rmax);
        *reinterpret_cast<float4*>(&sv[j4]) = v;
        lsum += v.x + v.y + v.z + v.w;
    }
    red[tid] = lsum; __syncthreads();
    for (int s = NT / 2; s > 0; s >>= 1) {
        if (tid < s) red[tid] += red[tid + s];
        __syncthreads();
    }
    float inv = 1.f / red[0]; __syncthreads();

    // pass 3: normalize, write P (float4), accumulate attn @ xyz
    float a0 = 0.f, a1 = 0.f, a2 = 0.f;
    for (int j4 = tid * 4; j4 < NN; j4 += NT * 4) {
        float4 v = *reinterpret_cast<float4*>(&sv[j4]);
        v.x *= inv; v.y *= inv; v.z *= inv; v.w *= inv;
        *reinterpret_cast<float4*>(&g_S[rowoff + j4]) = v;
        a0 += v.x * xyz[(j4 + 0) * 3]     + v.y * xyz[(j4 + 1) * 3]
            + v.z * xyz[(j4 + 2) * 3]     + v.w * xyz[(j4 + 3) * 3];
        a1 += v.x * xyz[(j4 + 0) * 3 + 1] + v.y * xyz[(j4 + 1) * 3 + 1]
            + v.z * xyz[(j4 + 2) * 3 + 1] + v.w * xyz[(j4 + 3) * 3 + 1];
        a2 += v.x * xyz[(j4 + 0) * 3 + 2] + v.y * xyz[(j4 + 1) * 3 + 2]
            + v.z * xyz[(j4 + 2) * 3 + 2] + v.w * xyz[(j4 + 3) * 3 + 2];
    }
    red[tid] = a0; __syncthreads();
    for (int s = NT / 2; s > 0; s >>= 1) { if (tid < s) red[tid] += red[tid + s]; __syncthreads(); }
    if (tid == 0) xyz_out[i * 3] = red[0];
    __syncthreads();
    red[tid] = a1; __syncthreads();
    for (int s = NT / 2; s > 0; s >>= 1) { if (tid < s) red[tid] += red[tid + s]; __syncthreads(); }
    if (tid == 0) xyz_out[i * 3 + 1] = red[0];
    __syncthreads();
    red[tid] = a2; __syncthreads();
    for (int s = NT / 2; s > 0; s >>= 1) { if (tid < s) red[tid] += red[tid + s]; __syncthreads(); }
    if (tid == 0) xyz_out[i * 3 + 2] = red[0];
}

// ---------------------------------------------------------------------------
// Host launcher
// ---------------------------------------------------------------------------
extern "C" void kernel_launch(void* const* d_in, const int* in_sizes, int n_in,
                              void* d_out, int out_size)
{
    (void)in_sizes; (void)n_in; (void)out_size;
    const float* feat  = (const float*)d_in[0];
    const float* xyz   = (const float*)d_in[1];
    const int*   src   = (const int*)  d_in[2];
    const int*   dst   = (const int*)  d_in[3];
    const void*  dmask = d_in[4];
    const void*  bmask = d_in[5];
    const float* fcW   = (const float*)d_in[6];
    const float* fcb   = (const float*)d_in[7];
    const float* gatW  = (const float*)d_in[8];
    const float* attnl = (const float*)d_in[9];
    const float* attnr = (const float*)d_in[10];
    const float* gcniiW= (const float*)d_in[11];
    const float* clsgW = (const float*)d_in[12];
    const float* clsgb = (const float*)d_in[13];
    const float* qW    = (const float*)d_in[14];
    const float* qb    = (const float*)d_in[15];
    const float* kW    = (const float*)d_in[16];
    const float* kb    = (const float*)d_in[17];
    const float* vW    = (const float*)d_in[18];
    const float* vb    = (const float*)d_in[19];
    const float* oW    = (const float*)d_in[20];
    const float* ob    = (const float*)d_in[21];
    const float* clsW  = (const float*)d_in[22];
    const float* clsb  = (const float*)d_in[23];

    float *pH0, *pX, *pH, *pCat, *pC, *pQ, *pK, *pV, *pHV, *pS;
    float *pXYZ0, *pXYZ1, *pYhat;
    int *pDeg, *pCnt;
    cudaGetSymbolAddress((void**)&pH0,  g_h0);
    cudaGetSymbolAddress((void**)&pX,   g_x);
    cudaGetSymbolAddress((void**)&pH,   g_H);
    cudaGetSymbolAddress((void**)&pCat, g_cat);
    cudaGetSymbolAddress((void**)&pC,   g_C);
    cudaGetSymbolAddress((void**)&pQ,   g_q);
    cudaGetSymbolAddress((void**)&pK,   g_k);
    cudaGetSymbolAddress((void**)&pV,   g_v);
    cudaGetSymbolAddress((void**)&pHV,  g_hv);
    cudaGetSymbolAddress((void**)&pS,   g_S);
    cudaGetSymbolAddress((void**)&pXYZ0, g_xyz0);
    cudaGetSymbolAddress((void**)&pXYZ1, g_xyz1);
    cudaGetSymbolAddress((void**)&pYhat, g_yhat);
    cudaGetSymbolAddress((void**)&pDeg, g_deg);
    cudaGetSymbolAddress((void**)&pCnt, g_cnt);

    const int T256 = 256;
    dim3 gVec4((NN * 64 + 255) / 256);        // NN*HIDD as float4
    dim3 gN64(HIDD / 64, NN / 128);           // M=4096, Nc=256 (BN=64): 128 CTAs
    dim3 gQKV(HIDD / 64, NN / 128, 3);        // batched q,k,v: 384 CTAs
    dim3 gS  (NN / 128, NN / 128);            // 4096x4096 (BN=128): 1024 CTAs

    // --- pair mask (dtype sniff + combine) ---
    detect_mask_kernel<<<1, 256>>>(dmask);
    {
        size_t total = (size_t)NN * NN;
        build_mask_kernel<<<(unsigned)((total + 255) / 256), 256>>>(dmask, bmask);
    }

    // --- CSR by dst (once; dst is layer-invariant) ---
    fill_int_kernel<<<(NN + 255) / 256, 256>>>(pDeg, 0, NN);
    fill_int_kernel<<<(NN + 255) / 256, 256>>>(pCnt, 0, NN);
    deg_count_kernel<<<EE / 256, 256>>>(dst);
    scan_kernel<<<1, 1024>>>();
    scatter_eid_kernel<<<EE / 256, 256>>>(dst);

    // --- h0 = relu(feat @ fcW + fcb), x = h0, cat right half = h0 ---
    gemm128_kernel<64,0,0,1><<<gN64, T256>>>(feat, fcW, fcb, pH0, NN, HIDD, FEATD, 1.f);
    copy4_kernel<<<gVec4, 256>>>(pH0, pX, NN * 64);
    cat_init_kernel<<<gVec4, 256>>>();

    // --- GAT + GCNII stack ---
    const float THETA[4] = {0.40546510f, 0.22314355f, 0.15415068f, 0.11778304f};
    for (int l = 0; l < 4; l++) {
        gemm128_kernel<64,0,0,0><<<gN64, T256>>>(pX, gatW + (size_t)l * HIDD * HIDD,
                                                 nullptr, pH, NN, HIDD, HIDD, 1.f);
        gat_attn_kernel<<<(NN * NHEAD + 255) / 256, 256>>>(pH, attnl + l * HIDD, attnr + l * HIDD);
        gat_init_kernel<<<(NN * NHEAD + 255) / 256, 256>>>();
        gat_edge1_kernel<<<(EE * NHEAD + 255) / 256, 256>>>(src, dst);
        gat_gather_kernel<<<NN / 4, 256>>>(src);
        // C = [xg | h0] @ gcnii_W[l]   (single K=512 GEMM)
        const float* Wl = gcniiW + (size_t)l * 2 * HIDD * HIDD;
        gemm128_kernel<64,0,0,0><<<gN64, T256>>>(pCat, Wl, nullptr, pC, NN, HIDD, 2 * HIDD, 1.f);
        gnn_combine_kernel<<<gVec4, 256>>>(THETA[l]);
    }

    // --- y_hat ---
    yhat_kernel<<<(NN + 255) / 256, 256>>>(clsgW, clsgb);

    // --- MS cluster stack ---
    copy_kernel<<<(NN * 3 + 255) / 256, 256>>>(xyz, pXYZ0, NN * 3);
    for (int l = 0; l < 4; l++) {
        float* cur = (l & 1) ? pXYZ1 : pXYZ0;
        float* nxt = (l & 1) ? pXYZ0 : pXYZ1;
        const size_t wo = (size_t)l * HIDD * HIDD;
        QKVArgs qa;
        qa.W[0] = qW + wo; qa.W[1] = kW + wo; qa.W[2] = vW + wo;
        qa.b[0] = qb + l * HIDD; qa.b[1] = kb + l * HIDD; qa.b[2] = vb + l * HIDD;
        qa.O[0] = pQ; qa.O[1] = pK; qa.O[2] = pV;
        gemm128_qkv_kernel<<<gQKV, T256>>>(pX, qa, NN, HIDD, HIDD);
        // S = masked, banded, delta_y-adjusted score (fused epilogue)
        gemm128_score_kernel<<<gS, T256>>>(pQ, pK, pS, cur, pYhat);
        ms_softmax_kernel<<<NN, 512>>>(cur, nxt);
        // hv = P @ v
        gemm128_kernel<64,0,0,0><<<gN64, T256>>>(pS, pV, nullptr, pHV, NN, HIDD, NN, 1.f);
        // x += hv @ oW + ob
        gemm128_kernel<64,0,1,0><<<gN64, T256>>>(pHV, oW + wo, ob + l * HIDD, pX, NN, HIDD, HIDD, 1.f);
    }

    // --- out = x @ clsW + clsb ---
    cls_kernel<<<(NN + 255) / 256, 256>>>(clsW, clsb, (float*)d_out);
}

// round 17
// speedup vs baseline: 1.0899x; 1.0899x over previous
#include <cuda_runtime.h>
#include <math.h>

// ---------------------------------------------------------------------------
// Problem constants (fixed shapes)
// ---------------------------------------------------------------------------
#define NN    4096
#define EE    131072
#define FEATD 64
#define HIDD  256
#define NHEAD 4
#define DHD   64
#define NEGV  (-1e9f)

// ---------------------------------------------------------------------------
// Device scratch (no dynamic allocation allowed)
// ---------------------------------------------------------------------------
__device__ float g_h0[NN * HIDD];
__device__ float g_x [NN * HIDD];
__device__ float g_H [NN * HIDD];
__device__ float g_cat[NN * 2 * HIDD];      // [xg | h0] concat, K=512 GEMM input
__device__ float g_q [NN * HIDD];
__device__ float g_k [NN * HIDD];
__device__ float g_v [NN * HIDD];
__device__ float g_hv[NN * HIDD];
__device__ float g_el[NN * NHEAD];
__device__ float g_er[NN * NHEAD];
__device__ float g_m [NN * NHEAD];
__device__ float g_we[EE * NHEAD];          // leaky-relu edge scores (immutable)
__device__ float g_yhat[NN];
__device__ float g_xyzA[3 * NN];            // SoA: [x[NN] | y[NN] | z[NN]]
__device__ float g_xyzB[3 * NN];
__device__ unsigned char g_mask[(size_t)NN * NN];
__device__ float g_S[(size_t)NN * NN];
__device__ int   g_mask_type;   // 0 = uint8, 1 = int32, 2 = float32
// CSR-by-dst (built once per launch; dst is layer-invariant)
__device__ int g_deg[NN];
__device__ int g_cnt[NN];
__device__ int g_off[NN + 1];
__device__ int g_eid[EE];

// ---------------------------------------------------------------------------
// Packed f32x2 helpers (Blackwell FFMA2 — only reachable via PTX)
// ---------------------------------------------------------------------------
__device__ __forceinline__ unsigned long long packf2(float x, float y) {
    unsigned long long r;
    asm("mov.b64 %0, {%1, %2};" : "=l"(r) : "f"(x), "f"(y));
    return r;
}
__device__ __forceinline__ void unpackf2(unsigned long long v, float& x, float& y) {
    asm("mov.b64 {%0, %1}, %2;" : "=f"(x), "=f"(y) : "l"(v));
}
__device__ __forceinline__ void ffma2(unsigned long long& d,
                                      unsigned long long a,
                                      unsigned long long b) {
    asm("fma.rn.f32x2 %0, %1, %2, %0;" : "+l"(d) : "l"(a), "l"(b));
}

__device__ __forceinline__ void atomicMaxFloat(float* addr, float val) {
    int* ia = (int*)addr;
    int old = *ia;
    while (__int_as_float(old) < val) {
        int assumed = old;
        old = atomicCAS(ia, assumed, __float_as_int(val));
        if (old == assumed) break;
    }
}

// ---------------------------------------------------------------------------
// Software-pipelined, double-buffered SGEMM with packed f32x2 FMA.
// A tiles live in SMEM pre-duplicated as u64 [a|a]. Ping-pong buffers give
// ONE __syncthreads per k-iteration.
//   C[M,Nc](ldc=Nc) = alpha * A[M,K] * op(B) (+bias) (+C) (relu)
//   op(B) = B[K,Nc] (TRANSB=0) or B[Nc,K]^T (TRANSB=1)
// MASKED=1 (score mode): out = mask && sqi+sqj-2dot<=100
//                              ? acc*alpha - |yhat_r-yhat_c| : NEGV
// GCNII=1 (combine mode): x = theta*acc + (1-theta)*(0.9*xg + 0.1*h0) + x
// FC=1 (fc mode): v = relu(acc+bias); write to C (g_h0), g_x, g_cat right half
// Tiles: BM=128 x BN=64 x BK=16, 256 threads, ~80 live regs.
// REQUIRES: M%128==0, Nc%BN==0, K%16==0.
// ---------------------------------------------------------------------------
template<int BN, int TRANSB, int ACC, int RELU, int MASKED = 0, int GCNII = 0, int FC = 0>
__device__ __forceinline__ void gemm128_body(const float* __restrict__ A,
                                             const float* __restrict__ B,
                                             const float* __restrict__ bias,
                                             float* __restrict__ C,
                                             int M, int Nc, int K, float alpha,
                                             const float* __restrict__ mxyz = nullptr,
                                             const float* __restrict__ myhat = nullptr)
{
    const int BM = 128, BK = 16;
    const int TN = BN / 16;
    const int J2 = BN / 32;
    const int NB = BN / 64;     // B float4 loads per thread (1 or 2)

    __shared__ unsigned long long As[2][BK][BM];   // duplicated-lane A
    __shared__ float Bs[2][BK][BN];

    int tid = threadIdx.x;
    int tx = tid & 15, ty = tid >> 4;
    int row0 = blockIdx.y * BM;
    int col0 = blockIdx.x * BN;

    const int ar0 = (tid + 0)   >> 2, ac0 = ((tid + 0)   & 3) * 4;
    const int ar1 = (tid + 256) >> 2, ac1 = ((tid + 256) & 3) * 4;

    unsigned long long acc[8][J2];
#pragma unroll
    for (int i = 0; i < 8; i++)
#pragma unroll
        for (int j = 0; j < J2; j++) acc[i][j] = 0ull;

    float4 aReg[2];
    float4 bReg[NB];

    // ---- prologue: load tile 0 into registers, stage into buffer 0 ----
    aReg[0] = *reinterpret_cast<const float4*>(A + (size_t)(row0 + ar0) * K + ac0);
    aReg[1] = *reinterpret_cast<const float4*>(A + (size_t)(row0 + ar1) * K + ac1);
#pragma unroll
    for (int t = 0; t < NB; t++) {
        int idx = tid + t * 256;
        if (TRANSB) {
            int r = idx >> 2, c4 = (idx & 3) * 4;
            bReg[t] = *reinterpret_cast<const float4*>(B + (size_t)(col0 + r) * K + c4);
        } else {
            int kk = idx / (BN / 4), c4 = (idx % (BN / 4)) * 4;
            bReg[t] = *reinterpret_cast<const float4*>(B + (size_t)kk * Nc + col0 + c4);
        }
    }
    As[0][ac0 + 0][ar0] = packf2(aReg[0].x, aReg[0].x);
    As[0][ac0 + 1][ar0] = packf2(aReg[0].y, aReg[0].y);
    As[0][ac0 + 2][ar0] = packf2(aReg[0].z, aReg[0].z);
    As[0][ac0 + 3][ar0] = packf2(aReg[0].w, aReg[0].w);
    As[0][ac1 + 0][ar1] = packf2(aReg[1].x, aReg[1].x);
    As[0][ac1 + 1][ar1] = packf2(aReg[1].y, aReg[1].y);
    As[0][ac1 + 2][ar1] = packf2(aReg[1].z, aReg[1].z);
    As[0][ac1 + 3][ar1] = packf2(aReg[1].w, aReg[1].w);
#pragma unroll
    for (int t = 0; t < NB; t++) {
        int idx = tid + t * 256;
        if (TRANSB) {
            int r = idx >> 2, c4 = (idx & 3) * 4;
            Bs[0][c4 + 0][r] = bReg[t].x; Bs[0][c4 + 1][r] = bReg[t].y;
            Bs[0][c4 + 2][r] = bReg[t].z; Bs[0][c4 + 3][r] = bReg[t].w;
        } else {
            int kk = idx / (BN / 4), c4 = (idx % (BN / 4)) * 4;
            *reinterpret_cast<float4*>(&Bs[0][kk][c4]) = bReg[t];
        }
    }
    __syncthreads();

    int cur = 0;
    for (int k0 = 0; k0 < K; k0 += BK) {
        int kn = k0 + BK;
        // ---- issue prefetch LDGs for next tile ----
        if (kn < K) {
            aReg[0] = *reinterpret_cast<const float4*>(A + (size_t)(row0 + ar0) * K + kn + ac0);
            aReg[1] = *reinterpret_cast<const float4*>(A + (size_t)(row0 + ar1) * K + kn + ac1);
#pragma unroll
            for (int t = 0; t < NB; t++) {
                int idx = tid + t * 256;
                if (TRANSB) {
                    int r = idx >> 2, c4 = (idx & 3) * 4;
                    bReg[t] = *reinterpret_cast<const float4*>(
                        B + (size_t)(col0 + r) * K + kn + c4);
                } else {
                    int kk = idx / (BN / 4), c4 = (idx % (BN / 4)) * 4;
                    bReg[t] = *reinterpret_cast<const float4*>(
                        B + (size_t)(kn + kk) * Nc + col0 + c4);
                }
            }
        }

        // ---- compute from current buffer ----
#pragma unroll
        for (int kk = 0; kk < BK; kk++) {
            unsigned long long a2[8];
            const unsigned long long* arow = &As[cur][kk][ty * 8];
#pragma unroll
            for (int i = 0; i < 8; i++) a2[i] = arow[i];
            const unsigned long long* brow =
                reinterpret_cast<const unsigned long long*>(&Bs[cur][kk][tx * TN]);
            unsigned long long b2[J2];
#pragma unroll
            for (int j = 0; j < J2; j++) b2[j] = brow[j];
#pragma unroll
            for (int i = 0; i < 8; i++)
#pragma unroll
                for (int j = 0; j < J2; j++) ffma2(acc[i][j], a2[i], b2[j]);
        }

        // ---- store next tile into the other buffer, single barrier ----
        if (kn < K) {
            int nxt = cur ^ 1;
            As[nxt][ac0 + 0][ar0] = packf2(aReg[0].x, aReg[0].x);
            As[nxt][ac0 + 1][ar0] = packf2(aReg[0].y, aReg[0].y);
            As[nxt][ac0 + 2][ar0] = packf2(aReg[0].z, aReg[0].z);
            As[nxt][ac0 + 3][ar0] = packf2(aReg[0].w, aReg[0].w);
            As[nxt][ac1 + 0][ar1] = packf2(aReg[1].x, aReg[1].x);
            As[nxt][ac1 + 1][ar1] = packf2(aReg[1].y, aReg[1].y);
            As[nxt][ac1 + 2][ar1] = packf2(aReg[1].z, aReg[1].z);
            As[nxt][ac1 + 3][ar1] = packf2(aReg[1].w, aReg[1].w);
#pragma unroll
            for (int t = 0; t < NB; t++) {
                int idx = tid + t * 256;
                if (TRANSB) {
                    int r = idx >> 2, c4 = (idx & 3) * 4;
                    Bs[nxt][c4 + 0][r] = bReg[t].x; Bs[nxt][c4 + 1][r] = bReg[t].y;
                    Bs[nxt][c4 + 2][r] = bReg[t].z; Bs[nxt][c4 + 3][r] = bReg[t].w;
                } else {
                    int kk = idx / (BN / 4), c4 = (idx % (BN / 4)) * 4;
                    *reinterpret_cast<float4*>(&Bs[nxt][kk][c4]) = bReg[t];
                }
            }
            __syncthreads();
            cur = nxt;
        }
    }

    // ---- epilogue ----
    if (MASKED) {
        const float* xs = mxyz;
        const float* ys = mxyz + NN;
        const float* zs = mxyz + 2 * NN;
        float cx0[TN], cx1[TN], cx2[TN], cy[TN], csq[TN];
#pragma unroll
        for (int j = 0; j < TN; j++) {
            int c = col0 + tx * TN + j;
            cx0[j] = xs[c];
            cx1[j] = ys[c];
            cx2[j] = zs[c];
            cy[j]  = myhat[c];
            csq[j] = cx0[j] * cx0[j] + cx1[j] * cx1[j] + cx2[j] * cx2[j];
        }
#pragma unroll
        for (int i = 0; i < 8; i++) {
            int r = row0 + ty * 8 + i;
            float rx0 = xs[r], rx1 = ys[r], rx2 = zs[r];
            float rsq = rx0 * rx0 + rx1 * rx1 + rx2 * rx2;
            float yi = myhat[r];
            const unsigned char* mrow = &g_mask[(size_t)r * NN + col0 + tx * TN];
#pragma unroll
            for (int j = 0; j < J2; j++) {
                int c = col0 + tx * TN + j * 2;
                float x, y;
                unpackf2(acc[i][j], x, y);
                x *= alpha; y *= alpha;
                float o0 = NEGV, o1 = NEGV;
                {
                    int jj = j * 2;
                    if (mrow[jj]) {
                        float dot = rx0 * cx0[jj] + rx1 * cx1[jj] + rx2 * cx2[jj];
                        float d2 = rsq + csq[jj] - 2.f * dot;   // reference formula
                        if (d2 <= 100.0f)
                            o0 = x - fabsf(yi - cy[jj]);
                    }
                    jj = j * 2 + 1;
                    if (mrow[jj]) {
                        float dot = rx0 * cx0[jj] + rx1 * cx1[jj] + rx2 * cx2[jj];
                        float d2 = rsq + csq[jj] - 2.f * dot;
                        if (d2 <= 100.0f)
                            o1 = y - fabsf(yi - cy[jj]);
                    }
                }
                *reinterpret_cast<float2*>(C + (size_t)r * Nc + c) = make_float2(o0, o1);
            }
        }
    } else if (GCNII) {
        // x = theta*acc + (1-theta)*(0.9*xg + 0.1*h0) + x     (theta = alpha)
        float om = 1.f - alpha;
#pragma unroll
        for (int i = 0; i < 8; i++) {
            int r = row0 + ty * 8 + i;
#pragma unroll
            for (int j = 0; j < J2; j++) {
                int c = col0 + tx * TN + j * 2;
                float x, y;
                unpackf2(acc[i][j], x, y);
                float2 xg = *reinterpret_cast<const float2*>(&g_cat[(size_t)r * 512 + c]);
                float2 h0 = *reinterpret_cast<const float2*>(&g_h0[(size_t)r * 256 + c]);
                float* cp = C + (size_t)r * Nc + c;
                float2 xo = *reinterpret_cast<float2*>(cp);
                xo.x = alpha * x + om * (0.9f * xg.x + 0.1f * h0.x) + xo.x;
                xo.y = alpha * y + om * (0.9f * xg.y + 0.1f * h0.y) + xo.y;
                *reinterpret_cast<float2*>(cp) = xo;
            }
        }
    } else if (FC) {
        // v = relu(acc + bias); write h0 (=C), g_x, g_cat right half
#pragma unroll
        for (int i = 0; i < 8; i++) {
            int r = row0 + ty * 8 + i;
#pragma unroll
            for (int j = 0; j < J2; j++) {
                int c = col0 + tx * TN + j * 2;
                float x, y;
                unpackf2(acc[i][j], x, y);
                x += bias[c]; y += bias[c + 1];
                x = fmaxf(x, 0.f); y = fmaxf(y, 0.f);
                float2 v = make_float2(x, y);
                *reinterpret_cast<float2*>(C + (size_t)r * Nc + c) = v;
                *reinterpret_cast<float2*>(&g_x[(size_t)r * 256 + c]) = v;
                *reinterpret_cast<float2*>(&g_cat[(size_t)r * 512 + 256 + c]) = v;
            }
        }
    } else {
#pragma unroll
        for (int i = 0; i < 8; i++) {
            int r = row0 + ty * 8 + i;
#pragma unroll
            for (int j = 0; j < J2; j++) {
                int c = col0 + tx * TN + j * 2;
                float x, y;
                unpackf2(acc[i][j], x, y);
                x *= alpha; y *= alpha;
                if (bias) { x += bias[c]; y += bias[c + 1]; }
                float* cp = C + (size_t)r * Nc + c;
                if (ACC) { float2 o = *reinterpret_cast<float2*>(cp); x += o.x; y += o.y; }
                if (RELU) { x = fmaxf(x, 0.f); y = fmaxf(y, 0.f); }
                *reinterpret_cast<float2*>(cp) = make_float2(x, y);
            }
        }
    }
}

template<int BN, int TRANSB, int ACC, int RELU>
__global__ void __launch_bounds__(256, 2)
gemm128_kernel(const float* __restrict__ A,
               const float* __restrict__ B,
               const float* __restrict__ bias,
               float* __restrict__ C,
               int M, int Nc, int K, float alpha)
{
    gemm128_body<BN, TRANSB, ACC, RELU>(A, B, bias, C, M, Nc, K, alpha);
}

// FC GEMM: h0 = relu(feat@W+b), also writes g_x and g_cat right half.
__global__ void __launch_bounds__(256, 2)
gemm128_fc_kernel(const float* __restrict__ A,
                  const float* __restrict__ B,
                  const float* __restrict__ bias,
                  float* __restrict__ H0)
{
    gemm128_body<64, 0, 0, 0, 0, 0, 1>(A, B, bias, H0, NN, HIDD, FEATD, 1.f);
}

// GCNII combine GEMM: x = theta*(cat@W) + (1-theta)*(0.9*xg + 0.1*h0) + x
__global__ void __launch_bounds__(256, 2)
gemm128_gcnii_kernel(const float* __restrict__ A,   // g_cat (K=512)
                     const float* __restrict__ B,   // gcnii W
                     float* __restrict__ X,         // g_x in/out
                     float theta)
{
    gemm128_body<64, 0, 0, 0, 0, 1>(A, B, nullptr, X, NN, HIDD, 2 * HIDD, theta);
}

// Masked score GEMM (BN=64): S = mask&band ? (q@k^T)/16 - |dy| : NEG
__global__ void __launch_bounds__(256, 2)
gemm128_score_kernel(const float* __restrict__ Q,
                     const float* __restrict__ Km,
                     float* __restrict__ S,
                     const float* __restrict__ xyz_soa,
                     const float* __restrict__ yhat)
{
    gemm128_body<64, 1, 0, 0, 1>(Q, Km, nullptr, S, NN, NN, HIDD, 1.f / 16.f,
                                 xyz_soa, yhat);
}

// Batched QKV projection: blockIdx.z selects {q,k,v}.
struct QKVArgs {
    const float* W[3];
    const float* b[3];
    float*       O[3];
};
__global__ void __launch_bounds__(256, 2)
gemm128_qkv_kernel(const float* __restrict__ A, QKVArgs args,
                   int M, int Nc, int K)
{
    int z = blockIdx.z;
    gemm128_body<64, 0, 0, 0>(A, args.W[z], args.b[z], args.O[z], M, Nc, K, 1.f);
}

// ---------------------------------------------------------------------------
// Small utility kernels
// ---------------------------------------------------------------------------
__global__ void fill_int_kernel(int* p, int v, int n) {
    int i = blockIdx.x * blockDim.x + threadIdx.x;
    if (i < n) p[i] = v;
}
// AoS xyz[N][3] -> SoA [x|y|z]
__global__ void xyz_transpose_kernel(const float* __restrict__ xyz_aos,
                                     float* __restrict__ soa) {
    int i = blockIdx.x * blockDim.x + threadIdx.x;
    if (i >= NN) return;
    soa[i]          = xyz_aos[i * 3];
    soa[NN + i]     = xyz_aos[i * 3 + 1];
    soa[2 * NN + i] = xyz_aos[i * 3 + 2];
}

// Bool-mask dtype sniffer: scans the first 4096 32-bit words of distance_mask.
__global__ void detect_mask_kernel(const void* p) {
    const unsigned int* w = (const unsigned int*)p;
    __shared__ int notbool, notfloat;
    if (threadIdx.x == 0) { notbool = 0; notfloat = 0; }
    __syncthreads();
    for (int j = threadIdx.x; j < 4096; j += blockDim.x) {
        unsigned int v = w[j];
        if (v > 1u) notbool = 1;                       // benign race
        if (v != 0u && v != 0x3F800000u) notfloat = 1;
    }
    __syncthreads();
    if (threadIdx.x == 0) {
        if (!notbool)       g_mask_type = 1;   // int32 0/1
        else if (!notfloat) g_mask_type = 2;   // float32 0/1
        else                g_mask_type = 0;   // uint8
    }
}

__global__ void build_mask_kernel(const void* dm, const void* bm) {
    size_t idx = (size_t)blockIdx.x * blockDim.x + threadIdx.x;
    size_t total = (size_t)NN * NN;
    if (idx >= total) return;
    int t = g_mask_type;
    bool a, b;
    if (t == 0) {
        a = ((const unsigned char*)dm)[idx] != 0;
        b = ((const unsigned char*)bm)[idx] != 0;
    } else if (t == 1) {
        a = ((const int*)dm)[idx] != 0;
        b = ((const int*)bm)[idx] != 0;
    } else {
        a = ((const float*)dm)[idx] != 0.f;
        b = ((const float*)bm)[idx] != 0.f;
    }
    g_mask[idx] = (a && b) ? 1 : 0;
}

// ---------------------------------------------------------------------------
// CSR-by-dst construction (once per launch)
// ---------------------------------------------------------------------------
__global__ void deg_count_kernel(const int* __restrict__ dst) {
    int e = blockIdx.x * blockDim.x + threadIdx.x;
    if (e < EE) atomicAdd(&g_deg[dst[e]], 1);
}

// Single-block Hillis-Steele inclusive scan over NN=4096 counts -> g_off
__global__ void scan_kernel() {
    __shared__ int bufA[NN], bufB[NN];
    int tid = threadIdx.x;                 // 1024 threads
    for (int i = tid; i < NN; i += 1024) bufA[i] = g_deg[i];
    __syncthreads();
    int* in = bufA; int* out = bufB;
    for (int s = 1; s < NN; s <<= 1) {
        for (int i = tid; i < NN; i += 1024)
            out[i] = in[i] + ((i >= s) ? in[i - s] : 0);
        __syncthreads();
        int* t = in; in = out; out = t;
    }
    if (tid == 0) g_off[0] = 0;
    for (int i = tid; i < NN; i += 1024) g_off[i + 1] = in[i];
}

__global__ void scatter_eid_kernel(const int* __restrict__ dst) {
    int e = blockIdx.x * blockDim.x + threadIdx.x;
    if (e >= EE) return;
    int d = dst[e];
    int pos = g_off[d] + atomicAdd(&g_cnt[d], 1);
    g_eid[pos] = e;
}

// ---------------------------------------------------------------------------
// GAT kernels
// ---------------------------------------------------------------------------
// Computes el/er AND initializes g_m (fused; same grid shape).
__global__ void gat_attn_kernel(const float* __restrict__ H,
                                const float* __restrict__ al,
                                const float* __restrict__ ar) {
    int idx = blockIdx.x * blockDim.x + threadIdx.x;   // N * NHEAD
    if (idx >= NN * NHEAD) return;
    int i = idx >> 2, h = idx & 3;
    const float* hp = H + (size_t)i * HIDD + h * DHD;
    const float* alp = al + h * DHD;
    const float* arp = ar + h * DHD;
    float sl = 0.f, sr = 0.f;
#pragma unroll 8
    for (int d = 0; d < DHD; d++) {
        float hv = hp[d];
        sl += hv * alp[d];
        sr += hv * arp[d];
    }
    g_el[idx] = sl;
    g_er[idx] = sr;
    g_m[idx]  = -3.0e38f;
}

// One thread per EDGE: loads src/dst once, float4 access to el/er/we.
__global__ void gat_edge1_kernel(const int* __restrict__ src,
                                 const int* __restrict__ dst) {
    int e = blockIdx.x * blockDim.x + threadIdx.x;
    if (e >= EE) return;
    int s = src[e], d = dst[e];
    float4 el = *reinterpret_cast<const float4*>(&g_el[s * NHEAD]);
    float4 er = *reinterpret_cast<const float4*>(&g_er[d * NHEAD]);
    float4 w;
    float t;
    t = el.x + er.x; w.x = t > 0.f ? t : 0.2f * t;
    t = el.y + er.y; w.y = t > 0.f ? t : 0.2f * t;
    t = el.z + er.z; w.z = t > 0.f ? t : 0.2f * t;
    t = el.w + er.w; w.w = t > 0.f ? t : 0.2f * t;
    *reinterpret_cast<float4*>(&g_we[e * NHEAD]) = w;
    atomicMaxFloat(&g_m[d * NHEAD + 0], w.x);
    atomicMaxFloat(&g_m[d * NHEAD + 1], w.y);
    atomicMaxFloat(&g_m[d * NHEAD + 2], w.z);
    atomicMaxFloat(&g_m[d * NHEAD + 3], w.w);
}

// CSR gather with fused edge-softmax normalization.
// 4 dst nodes per block (256 thr = 4 x 64); each thread owns 4 channels.
__global__ void gat_gather_kernel(const int* __restrict__ src) {
    int tid = threadIdx.x;
    int d  = blockIdx.x * 4 + (tid >> 6);   // dst node
    int t64 = tid & 63;                     // 0..63
    int c4 = t64 * 4;                       // channel base (0..252)
    int h = c4 >> 6;                        // head (4 channels share a head)
    float m = g_m[d * NHEAD + h];
    int p0 = g_off[d], p1 = g_off[d + 1];

    // pass A: normalization constant
    float z = 0.f;
    for (int p = p0; p < p1; p++) {
        int e = g_eid[p];
        z += __expf(g_we[e * NHEAD + h] - m);
    }
    float inv = 1.f / (z + 1e-9f);

    // pass B: weighted feature accumulation
    float4 acc = make_float4(0.f, 0.f, 0.f, 0.f);
    for (int p = p0; p < p1; p++) {
        int e = g_eid[p];
        float a = __expf(g_we[e * NHEAD + h] - m) * inv;
        float4 hv = *reinterpret_cast<const float4*>(
            &g_H[(size_t)src[e] * HIDD + c4]);
        acc.x += a * hv.x; acc.y += a * hv.y;
        acc.z += a * hv.z; acc.w += a * hv.w;
    }
    *reinterpret_cast<float4*>(&g_cat[(size_t)d * 512 + c4]) = acc;
}

// ---------------------------------------------------------------------------
// y_hat = softmax(x @ cls_gat_W + b)[:, 1]   (float4 row loads)
// ---------------------------------------------------------------------------
__global__ void yhat_kernel(const float* __restrict__ W, const float* __restrict__ b) {
    int i = blockIdx.x * blockDim.x + threadIdx.x;
    if (i >= NN) return;
    float l0 = b[0], l1 = b[1];
    const float4* xp = reinterpret_cast<const float4*>(g_x + (size_t)i * HIDD);
#pragma unroll 4
    for (int k4 = 0; k4 < HIDD / 4; k4++) {
        float4 xv = xp[k4];
        int kk = k4 * 4;
        l0 += xv.x * W[(kk + 0) * 2]; l1 += xv.x * W[(kk + 0) * 2 + 1];
        l0 += xv.y * W[(kk + 1) * 2]; l1 += xv.y * W[(kk + 1) * 2 + 1];
        l0 += xv.z * W[(kk + 2) * 2]; l1 += xv.z * W[(kk + 2) * 2 + 1];
        l0 += xv.w * W[(kk + 3) * 2]; l1 += xv.w * W[(kk + 3) * 2 + 1];
    }
    float m = fmaxf(l0, l1);
    float e0 = __expf(l0 - m), e1 = __expf(l1 - m);
    g_yhat[i] = e1 / (e0 + e1);
}

// Final classifier: out[i,:] = x[i,:] @ clsW + clsb   (Nc = 2, float4 loads)
__global__ void cls_kernel(const float* __restrict__ W,
                           const float* __restrict__ b,
                           float* __restrict__ out) {
    int i = blockIdx.x * blockDim.x + threadIdx.x;
    if (i >= NN) return;
    float l0 = b[0], l1 = b[1];
    const float4* xp = reinterpret_cast<const float4*>(g_x + (size_t)i * HIDD);
#pragma unroll 4
    for (int k4 = 0; k4 < HIDD / 4; k4++) {
        float4 xv = xp[k4];
        int kk = k4 * 4;
        l0 += xv.x * W[(kk + 0) * 2]; l1 += xv.x * W[(kk + 0) * 2 + 1];
        l0 += xv.y * W[(kk + 1) * 2]; l1 += xv.y * W[(kk + 1) * 2 + 1];
        l0 += xv.z * W[(kk + 2) * 2]; l1 += xv.z * W[(kk + 2) * 2 + 1];
        l0 += xv.w * W[(kk + 3) * 2]; l1 += xv.w * W[(kk + 3) * 2 + 1];
    }
    out[i * 2 + 0] = l0;
    out[i * 2 + 1] = l1;
}

// ---------------------------------------------------------------------------
// Softmax over a pre-masked score row (held in SMEM) + fused attn @ xyz.
// xyz in SoA [x|y|z]; all row passes and coordinate loads are float4.
// ---------------------------------------------------------------------------
__global__ void ms_softmax_kernel(const float* __restrict__ xyz_soa,
                                  float* __restrict__ xyz_out_soa)
{
    __shared__ float sv[NN];
    __shared__ float red[512];
    const int NT = 512;
    int i = blockIdx.x, tid = threadIdx.x;
    size_t rowoff = (size_t)i * NN;
    const float* xs = xyz_soa;
    const float* ys = xyz_soa + NN;
    const float* zs = xyz_soa + 2 * NN;

    // pass 1: load scores (float4), track max
    float lmax = -3.4e38f;
    for (int j4 = tid * 4; j4 < NN; j4 += NT * 4) {
        float4 v = *reinterpret_cast<const float4*>(&g_S[rowoff + j4]);
        *reinterpret_cast<float4*>(&sv[j4]) = v;
        lmax = fmaxf(lmax, fmaxf(fmaxf(v.x, v.y), fmaxf(v.z, v.w)));
    }
    red[tid] = lmax; __syncthreads();
    for (int s = NT / 2; s > 0; s >>= 1) {
        if (tid < s) red[tid] = fmaxf(red[tid], red[tid + s]);
        __syncthreads();
    }
    float rmax = red[0]; __syncthreads();

    // pass 2: exp + sum (float4)
    float lsum = 0.f;
    for (int j4 = tid * 4; j4 < NN; j4 += NT * 4) {
        float4 v = *reinterpret_cast<float4*>(&sv[j4]);
        v.x = __expf(v.x - rmax); v.y = __expf(v.y - rmax);
        v.z = __expf(v.z - rmax); v.w = __expf(v.w - rmax);
        *reinterpret_cast<float4*>(&sv[j4]) = v;
        lsum += v.x + v.y + v.z + v.w;
    }
    red[tid] = lsum; __syncthreads();
    for (int s = NT / 2; s > 0; s >>= 1) {
        if (tid < s) red[tid] += red[tid + s];
        __syncthreads();
    }
    float inv = 1.f / red[0]; __syncthreads();

    // pass 3: normalize, write P (float4), accumulate attn @ xyz (SoA float4)
    float a0 = 0.f, a1 = 0.f, a2 = 0.f;
    for (int j4 = tid * 4; j4 < NN; j4 += NT * 4) {
        float4 v = *reinterpret_cast<float4*>(&sv[j4]);
        v.x *= inv; v.y *= inv; v.z *= inv; v.w *= inv;
        *reinterpret_cast<float4*>(&g_S[rowoff + j4]) = v;
        float4 px = *reinterpret_cast<const float4*>(&xs[j4]);
        float4 py = *reinterpret_cast<const float4*>(&ys[j4]);
        float4 pz = *reinterpret_cast<const float4*>(&zs[j4]);
        a0 += v.x * px.x + v.y * px.y + v.z * px.z + v.w * px.w;
        a1 += v.x * py.x + v.y * py.y + v.z * py.z + v.w * py.w;
        a2 += v.x * pz.x + v.y * pz.y + v.z * pz.z + v.w * pz.w;
    }
    red[tid] = a0; __syncthreads();
    for (int s = NT / 2; s > 0; s >>= 1) { if (tid < s) red[tid] += red[tid + s]; __syncthreads(); }
    if (tid == 0) xyz_out_soa[i] = red[0];
    __syncthreads();
    red[tid] = a1; __syncthreads();
    for (int s = NT / 2; s > 0; s >>= 1) { if (tid < s) red[tid] += red[tid + s]; __syncthreads(); }
    if (tid == 0) xyz_out_soa[NN + i] = red[0];
    __syncthreads();
    red[tid] = a2; __syncthreads();
    for (int s = NT / 2; s > 0; s >>= 1) { if (tid < s) red[tid] += red[tid + s]; __syncthreads(); }
    if (tid == 0) xyz_out_soa[2 * NN + i] = red[0];
}

// ---------------------------------------------------------------------------
// Host launcher
// ---------------------------------------------------------------------------
extern "C" void kernel_launch(void* const* d_in, const int* in_sizes, int n_in,
                              void* d_out, int out_size)
{
    (void)in_sizes; (void)n_in; (void)out_size;
    const float* feat  = (const float*)d_in[0];
    const float* xyz   = (const float*)d_in[1];
    const int*   src   = (const int*)  d_in[2];
    const int*   dst   = (const int*)  d_in[3];
    const void*  dmask = d_in[4];
    const void*  bmask = d_in[5];
    const float* fcW   = (const float*)d_in[6];
    const float* fcb   = (const float*)d_in[7];
    const float* gatW  = (const float*)d_in[8];
    const float* attnl = (const float*)d_in[9];
    const float* attnr = (const float*)d_in[10];
    const float* gcniiW= (const float*)d_in[11];
    const float* clsgW = (const float*)d_in[12];
    const float* clsgb = (const float*)d_in[13];
    const float* qW    = (const float*)d_in[14];
    const float* qb    = (const float*)d_in[15];
    const float* kW    = (const float*)d_in[16];
    const float* kb    = (const float*)d_in[17];
    const float* vW    = (const float*)d_in[18];
    const float* vb    = (const float*)d_in[19];
    const float* oW    = (const float*)d_in[20];
    const float* ob    = (const float*)d_in[21];
    const float* clsW  = (const float*)d_in[22];
    const float* clsb  = (const float*)d_in[23];

    float *pH0, *pX, *pH, *pCat, *pQ, *pK, *pV, *pHV, *pS;
    float *pXYZA, *pXYZB, *pYhat;
    int *pDeg, *pCnt;
    cudaGetSymbolAddress((void**)&pH0,  g_h0);
    cudaGetSymbolAddress((void**)&pX,   g_x);
    cudaGetSymbolAddress((void**)&pH,   g_H);
    cudaGetSymbolAddress((void**)&pCat, g_cat);
    cudaGetSymbolAddress((void**)&pQ,   g_q);
    cudaGetSymbolAddress((void**)&pK,   g_k);
    cudaGetSymbolAddress((void**)&pV,   g_v);
    cudaGetSymbolAddress((void**)&pHV,  g_hv);
    cudaGetSymbolAddress((void**)&pS,   g_S);
    cudaGetSymbolAddress((void**)&pXYZA, g_xyzA);
    cudaGetSymbolAddress((void**)&pXYZB, g_xyzB);
    cudaGetSymbolAddress((void**)&pYhat, g_yhat);
    cudaGetSymbolAddress((void**)&pDeg, g_deg);
    cudaGetSymbolAddress((void**)&pCnt, g_cnt);

    const int T256 = 256;
    dim3 gN64(HIDD / 64, NN / 128);           // M=4096, Nc=256 (BN=64): 128 CTAs
    dim3 gQKV(HIDD / 64, NN / 128, 3);        // batched q,k,v: 384 CTAs
    dim3 gS  (NN / 64, NN / 128);             // 4096x4096 (BN=64): 2048 CTAs

    // --- CSR by dst first (5 tiny launches) so the ncu capture index (~6)
    //     lands on the first big FFMA2 GEMM and yields useful SASS/stalls ---
    fill_int_kernel<<<(NN + 255) / 256, 256>>>(pDeg, 0, NN);
    fill_int_kernel<<<(NN + 255) / 256, 256>>>(pCnt, 0, NN);
    deg_count_kernel<<<EE / 256, 256>>>(dst);
    scan_kernel<<<1, 1024>>>();
    scatter_eid_kernel<<<EE / 256, 256>>>(dst);

    // --- h0 = relu(feat @ fcW + fcb); epilogue also writes g_x and cat ---
    gemm128_fc_kernel<<<gN64, T256>>>(feat, fcW, fcb, pH0);

    // --- GAT + GCNII stack ---
    const float THETA[4] = {0.40546510f, 0.22314355f, 0.15415068f, 0.11778304f};
    for (int l = 0; l < 4; l++) {
        gemm128_kernel<64,0,0,0><<<gN64, T256>>>(pX, gatW + (size_t)l * HIDD * HIDD,
                                                 nullptr, pH, NN, HIDD, HIDD, 1.f);
        gat_attn_kernel<<<(NN * NHEAD + 255) / 256, 256>>>(pH, attnl + l * HIDD, attnr + l * HIDD);
        gat_edge1_kernel<<<EE / 256, 256>>>(src, dst);
        gat_gather_kernel<<<NN / 4, 256>>>(src);
        // x = theta*([xg|h0] @ W) + (1-theta)*(0.9*xg + 0.1*h0) + x  (fused)
        const float* Wl = gcniiW + (size_t)l * 2 * HIDD * HIDD;
        gemm128_gcnii_kernel<<<gN64, T256>>>(pCat, Wl, pX, THETA[l]);
    }

    // --- y_hat ---
    yhat_kernel<<<(NN + 255) / 256, 256>>>(clsgW, clsgb);

    // --- pair mask (needed only by the MS score GEMMs) ---
    detect_mask_kernel<<<1, 256>>>(dmask);
    {
        size_t total = (size_t)NN * NN;
        build_mask_kernel<<<(unsigned)((total + 255) / 256), 256>>>(dmask, bmask);
    }

    // --- MS cluster stack (xyz in SoA) ---
    xyz_transpose_kernel<<<(NN + 255) / 256, 256>>>(xyz, pXYZA);
    for (int l = 0; l < 4; l++) {
        float* cur = (l & 1) ? pXYZB : pXYZA;
        float* nxt = (l & 1) ? pXYZA : pXYZB;
        const size_t wo = (size_t)l * HIDD * HIDD;
        QKVArgs qa;
        qa.W[0] = qW + wo; qa.W[1] = kW + wo; qa.W[2] = vW + wo;
        qa.b[0] = qb + l * HIDD; qa.b[1] = kb + l * HIDD; qa.b[2] = vb + l * HIDD;
        qa.O[0] = pQ; qa.O[1] = pK; qa.O[2] = pV;
        gemm128_qkv_kernel<<<gQKV, T256>>>(pX, qa, NN, HIDD, HIDD);
        // S = masked, banded, delta_y-adjusted score (fused epilogue, BN=64)
        gemm128_score_kernel<<<gS, T256>>>(pQ, pK, pS, cur, pYhat);
        ms_softmax_kernel<<<NN, 512>>>(cur, nxt);
        // hv = P @ v
        gemm128_kernel<64,0,0,0><<<gN64, T256>>>(pS, pV, nullptr, pHV, NN, HIDD, NN, 1.f);
        // x += hv @ oW + ob
        gemm128_kernel<64,0,1,0><<<gN64, T256>>>(pHV, oW + wo, ob + l * HIDD, pX, NN, HIDD, HIDD, 1.f);
    }

    // --- out = x @ clsW + clsb ---
    cls_kernel<<<(NN + 255) / 256, 256>>>(clsW, clsb, (float*)d_out);
}